// round 3
// baseline (speedup 1.0000x reference)
#include <cuda_runtime.h>
#include <math.h>

#define H 1024
#define H4 256        // H/4
#define L 256
#define V 32000
#define NB 128
#define NT 1024

// ---------------- persistent device state ----------------
__device__ float g_xemb[L*H];
__device__ float g_E[L*H];
__device__ float g_Ew2[L*H];
__device__ float g_h[2][H];
__device__ float g_c[H];
__device__ float g_gates[4*H];
__device__ float g_w1h[H];
__device__ float g_scores[L];
__device__ float g_xin[2*H];            // [relu(prev_emb) | ctx]
__device__ unsigned long long g_part[NB];
__device__ unsigned g_count;
__device__ volatile unsigned g_epoch;

// ---------------- init (graph node 1) ----------------
__global__ void init_kernel() {
    int t = threadIdx.x;
    if (t == 0) { g_count = 0; g_epoch = 0; }
    g_h[0][t] = 0.f; g_h[1][t] = 0.f; g_c[t] = 0.f;
    g_xin[t] = 0.f;  g_xin[H + t] = 0.f;
}

// ---------------- helpers ----------------
__device__ __forceinline__ void gsync(unsigned target) {
    __syncthreads();
    if (threadIdx.x == 0) {
        __threadfence();
        if (atomicAdd(&g_count, 1u) == gridDim.x - 1u) {
            g_count = 0;
            __threadfence();
            g_epoch = target;
        } else {
            while (g_epoch < target) { }
        }
    }
    __syncthreads();
}

__device__ __forceinline__ float warp_red(float v) {
    #pragma unroll
    for (int o = 16; o > 0; o >>= 1) v += __shfl_down_sync(0xffffffffu, v, o);
    return v;
}

__device__ __forceinline__ float dot4(const float4 w, const float4 a) {
    return fmaf(w.x, a.x, fmaf(w.y, a.y, fmaf(w.z, a.z, w.w * a.w)));
}

// w1 @ h -> g_w1h, executed by blocks 0..31 (warp per row)
__device__ __forceinline__ void w1h_phase(int b, int tid, int warp, int lane,
                                          const float* hsrc, float* s_h,
                                          const float* __restrict__ w1) {
    float4* sh = (float4*)s_h;
    const float4* hv = (const float4*)hsrc;
    for (int k = tid; k < H4; k += NT) sh[k] = __ldcg(hv + k);
    __syncthreads();
    int r = b * 32 + warp;
    const float4* wr = (const float4*)(w1 + (size_t)r * H);
    float s = 0.f;
    #pragma unroll 4
    for (int k = lane; k < H4; k += 32) s += dot4(wr[k], sh[k]);
    s = warp_red(s);
    if (lane == 0) g_w1h[r] = s;
}

// ---------------- the whole model (graph node 2) ----------------
__global__ void __launch_bounds__(NT, 1) model_kernel(
    const int*   __restrict__ seq,   const float* __restrict__ embeds,
    const float* __restrict__ eWih,  const float* __restrict__ eWhh,
    const float* __restrict__ ebih,  const float* __restrict__ ebhh,
    const float* __restrict__ dWih,  const float* __restrict__ dWhh,
    const float* __restrict__ dbih,  const float* __restrict__ dbhh,
    const float* __restrict__ outW,  const float* __restrict__ outb,
    const float* __restrict__ v,     const float* __restrict__ w1,
    const float* __restrict__ w2,
    float* __restrict__ out, float* __restrict__ out_seq)
{
    const int b = blockIdx.x, tid = threadIdx.x;
    const int warp = tid >> 5, lane = tid & 31;
    unsigned ep = 0;

    __shared__ float s_vec[2*H];                 // 8 KB staged xin / x
    __shared__ float s_h[H];                     // 4 KB staged h / w1h / E-row
    __shared__ float s_sc[L];                    // 1 KB scores
    __shared__ float s_red[32];
    __shared__ unsigned long long s_key[32];
    __shared__ float s_r2[NT];                   // 4 KB group reductions

    // ---- embedding gather ----
    for (int t = b; t < L; t += NB) {
        int id = seq[t];
        const float* src = embeds + (size_t)id * H;
        for (int k = tid; k < H; k += NT) g_xemb[t*H + k] = src[k];
    }
    gsync(++ep);

    // ---- encoder: 256 steps, 2 barriers each ----
    for (int t = 0; t < L; t++) {
        {
            const float4* xv = (const float4*)(g_xemb + t*H);
            const float4* hv = (const float4*)g_h[t & 1];
            float4* sv = (float4*)s_vec;
            float4* sh = (float4*)s_h;
            for (int k = tid; k < H4; k += NT) { sv[k] = xv[k]; sh[k] = __ldcg(hv + k); }
            __syncthreads();
            int r = b * 32 + warp;                       // 4096 gate rows, warp each
            const float4* wi = (const float4*)(eWih + (size_t)r * H);
            const float4* wh = (const float4*)(eWhh + (size_t)r * H);
            float s = 0.f;
            #pragma unroll 4
            for (int k = lane; k < H4; k += 32) {
                s += dot4(wi[k], sv[k]);
                s += dot4(wh[k], sh[k]);
            }
            s = warp_red(s);
            if (lane == 0) g_gates[r] = s + ebih[r] + ebhh[r];
        }
        gsync(++ep);
        if (tid < 8) {                                   // block b owns units b*8..b*8+7
            int j = b * 8 + tid;
            float gi = __ldcg(g_gates + j);
            float gf = __ldcg(g_gates + H + j);
            float gg = __ldcg(g_gates + 2*H + j);
            float go = __ldcg(g_gates + 3*H + j);
            float i_ = 1.f / (1.f + expf(-gi));
            float f_ = 1.f / (1.f + expf(-gf));
            float o_ = 1.f / (1.f + expf(-go));
            float cn = f_ * g_c[j] + i_ * tanhf(gg);
            float hn = o_ * tanhf(cn);
            g_c[j] = cn;
            g_h[(t+1)&1][j] = hn;
            g_E[t*H + j] = hn;
        }
        gsync(++ep);
    }

    // ---- Ew2 = E @ w2^T (one-time): block b does E rows 2b, 2b+1 ----
    for (int rr = 0; rr < 2; rr++) {
        int i = 2*b + rr;
        const float4* Er = (const float4*)(g_E + i*H);
        float4* sh = (float4*)s_h;
        for (int k = tid; k < H4; k += NT) sh[k] = Er[k];
        __syncthreads();
        for (int j = warp; j < H; j += 32) {
            const float4* wr = (const float4*)(w2 + (size_t)j * H);
            float s = 0.f;
            #pragma unroll 4
            for (int k = lane; k < H4; k += 32) s += dot4(wr[k], sh[k]);
            s = warp_red(s);
            if (lane == 0) g_Ew2[i*H + j] = s;
        }
        __syncthreads();
    }
    gsync(++ep);

    // ---- A0: w1 @ h for first decoder step ----
    if (b < 32) w1h_phase(b, tid, warp, lane, g_h[0], s_h, w1);
    gsync(++ep);

    // ---- decoder: 256 steps, 6 barriers each ----
    for (int d = 0; d < L; d++) {
        const int pin = d & 1, pout = (d + 1) & 1;

        // B: scores_i = v . tanh(w1h + Ew2[i])   (block b -> rows 2b, 2b+1)
        {
            float4* sh = (float4*)s_h;
            const float4* wv = (const float4*)g_w1h;
            for (int k = tid; k < H4; k += NT) sh[k] = __ldcg(wv + k);
            __syncthreads();
            for (int rr = 0; rr < 2; rr++) {
                int i = 2*b + rr;
                float val = v[tid] * tanhf(s_h[tid] + g_Ew2[i*H + tid]);
                val = warp_red(val);
                if (lane == 0) s_red[warp] = val;
                __syncthreads();
                if (warp == 0) {
                    float x = warp_red(s_red[lane]);
                    if (lane == 0) g_scores[i] = x;
                }
                __syncthreads();
            }
        }
        gsync(++ep);

        // C: softmax (redundant per block) + ctx slice -> g_xin[H..)
        {
            if (tid < L) s_sc[tid] = __ldcg(g_scores + tid);
            __syncthreads();
            float mval = (tid < L) ? s_sc[tid] : -3.0e38f;
            #pragma unroll
            for (int o = 16; o > 0; o >>= 1)
                mval = fmaxf(mval, __shfl_down_sync(0xffffffffu, mval, o));
            if (lane == 0) s_red[warp] = mval;
            __syncthreads();
            if (tid == 0) {
                float mm = s_red[0];
                for (int w_ = 1; w_ < 32; w_++) mm = fmaxf(mm, s_red[w_]);
                s_red[0] = mm;
            }
            __syncthreads();
            float mx = s_red[0];
            float ev = 0.f;
            if (tid < L) { ev = expf(s_sc[tid] - mx); }
            __syncthreads();
            if (tid < L) s_sc[tid] = ev;
            float sv2 = warp_red(ev);
            if (lane == 0) s_red[warp] = sv2;
            __syncthreads();
            if (tid == 0) {
                float ss = 0.f;
                for (int w_ = 0; w_ < 32; w_++) ss += s_red[w_];
                s_red[0] = 1.f / ss;
            }
            __syncthreads();
            float inv = s_red[0];
            int q = tid >> 7, ii = tid & 127;
            int j = b * 8 + q;
            float acc = s_sc[ii]       * g_E[ii*H + j]
                      + s_sc[ii + 128] * g_E[(ii + 128)*H + j];
            s_r2[tid] = acc;
            __syncthreads();
            for (int st = 64; st > 0; st >>= 1) {
                if (ii < st) s_r2[tid] += s_r2[tid + st];
                __syncthreads();
            }
            if (ii == 0) g_xin[H + j] = s_r2[tid] * inv;
        }
        gsync(++ep);

        // D: decoder LSTM gate rows (warp per row)
        {
            float4* sv = (float4*)s_vec;
            float4* sh = (float4*)s_h;
            const float4* xv = (const float4*)g_xin;
            const float4* hv = (const float4*)g_h[pin];
            for (int k = tid; k < 2*H4; k += NT) sv[k] = __ldcg(xv + k);
            for (int k = tid; k < H4;   k += NT) sh[k] = __ldcg(hv + k);
            __syncthreads();
            int r = b * 32 + warp;
            const float4* wi = (const float4*)(dWih + (size_t)r * 2 * H);
            const float4* wh = (const float4*)(dWhh + (size_t)r * H);
            float s = 0.f;
            #pragma unroll 4
            for (int k = lane; k < 2*H4; k += 32) s += dot4(wi[k], sv[k]);
            #pragma unroll 4
            for (int k = lane; k < H4;   k += 32) s += dot4(wh[k], sh[k]);
            s = warp_red(s);
            if (lane == 0) g_gates[r] = s + dbih[r] + dbhh[r];
        }
        gsync(++ep);

        // combine -> h_new, c
        if (tid < 8) {
            int j = b * 8 + tid;
            float gi = __ldcg(g_gates + j);
            float gf = __ldcg(g_gates + H + j);
            float gg = __ldcg(g_gates + 2*H + j);
            float go = __ldcg(g_gates + 3*H + j);
            float i_ = 1.f / (1.f + expf(-gi));
            float f_ = 1.f / (1.f + expf(-gf));
            float o_ = 1.f / (1.f + expf(-go));
            float cn = f_ * g_c[j] + i_ * tanhf(gg);
            float hn = o_ * tanhf(cn);
            g_c[j] = cn;
            g_h[pout][j] = hn;
        }
        gsync(++ep);

        // E: logits = out_W @ h_new + out_b  (streamed, evict-first) + block argmax partial
        {
            float4* sh = (float4*)s_h;
            const float4* hv = (const float4*)g_h[pout];
            for (int k = tid; k < H4; k += NT) sh[k] = __ldcg(hv + k);
            __syncthreads();
            float bestv = -3.0e38f; int bestr = 0;
            float* od = out + (size_t)d * V;
            for (int r = b * 32 + warp; r < V; r += NB * 32) {
                const float4* wr = (const float4*)(outW + (size_t)r * H);
                float s = 0.f;
                #pragma unroll 4
                for (int k = lane; k < H4; k += 32) s += dot4(__ldcs(wr + k), sh[k]);
                s = warp_red(s);
                if (lane == 0) {
                    s += outb[r];
                    od[r] = s;
                    if (s > bestv) { bestv = s; bestr = r; }   // rows increase -> first-max kept
                }
            }
            if (lane == 0) {
                unsigned u = __float_as_uint(bestv);
                u = (u & 0x80000000u) ? ~u : (u | 0x80000000u);
                s_key[warp] = ((unsigned long long)u << 32) |
                              (unsigned long long)(0xFFFFFFFFu - (unsigned)bestr);
            }
            __syncthreads();
            if (tid == 0) {
                unsigned long long kk = s_key[0];
                for (int w_ = 1; w_ < 32; w_++) if (s_key[w_] > kk) kk = s_key[w_];
                g_part[b] = kk;
            }
        }
        gsync(++ep);

        // F || A': blocks 0..31 compute next-step w1h; blocks 32..40 finish argmax + feedback
        if (b < 32) {
            w1h_phase(b, tid, warp, lane, g_h[pout], s_h, w1);
        } else if (b < 41) {
            unsigned long long kk = (tid < NB) ? __ldcg(g_part + tid) : 0ull;
            #pragma unroll
            for (int o = 16; o > 0; o >>= 1) {
                unsigned long long ok = __shfl_down_sync(0xffffffffu, kk, o);
                if (ok > kk) kk = ok;
            }
            if (lane == 0) s_key[warp] = kk;
            __syncthreads();
            if (tid == 0) {
                unsigned long long m2 = s_key[0];
                for (int w_ = 1; w_ < 32; w_++) if (s_key[w_] > m2) m2 = s_key[w_];
                s_key[0] = m2;
            }
            __syncthreads();
            int idx = (int)(0xFFFFFFFFu - (unsigned)(s_key[0] & 0xFFFFFFFFull));
            if (b == 40) {
                if (tid == 0 && out_seq) out_seq[d] = (float)idx;
            } else {
                int base = (b - 32) * 128;
                if (tid < 128) {
                    float e = embeds[(size_t)idx * H + base + tid];
                    g_xin[base + tid] = fmaxf(e, 0.f);
                }
            }
        }
        gsync(++ep);
    }
}

// ---------------- launch: 2-node graph ----------------
extern "C" void kernel_launch(void* const* d_in, const int* in_sizes, int n_in,
                              void* d_out, int out_size)
{
    const int*   seq    = (const int*)  d_in[0];
    const float* embeds = (const float*)d_in[1];
    const float* eWih = (const float*)d_in[2],  *eWhh = (const float*)d_in[3];
    const float* ebih = (const float*)d_in[4],  *ebhh = (const float*)d_in[5];
    const float* dWih = (const float*)d_in[6],  *dWhh = (const float*)d_in[7];
    const float* dbih = (const float*)d_in[8],  *dbhh = (const float*)d_in[9];
    const float* outW = (const float*)d_in[10], *outb = (const float*)d_in[11];
    const float* v    = (const float*)d_in[12];
    const float* w1   = (const float*)d_in[13], *w2   = (const float*)d_in[14];

    float* out = (float*)d_out;
    float* out_seq = (out_size >= L*V + L) ? out + (size_t)L*V : nullptr;

    init_kernel<<<1, NT>>>();
    model_kernel<<<NB, NT>>>(seq, embeds, eWih, eWhh, ebih, ebhh,
                             dWih, dWhh, dbih, dbhh, outW, outb,
                             v, w1, w2, out, out_seq);
}

// round 4
// speedup vs baseline: 1.3424x; 1.3424x over previous
#include <cuda_runtime.h>
#include <cuda_fp16.h>
#include <math.h>

#define H 1024
#define H4 256        // H/4
#define L 256
#define V 32000
#define NB 128
#define NT 1024

// ---------------- persistent device state ----------------
__device__ float g_xemb[L*H];
__device__ float g_E[L*H];
__device__ float g_Ew2[L*H];
__device__ float g_h[2][H];
__device__ float g_w1h[H];
__device__ float g_scores[L];
__device__ float g_xin[2*H];            // [relu(prev_emb) | ctx]
__device__ unsigned long long g_part[NB];
__device__ unsigned g_count;
__device__ volatile unsigned g_epoch;

// fp16 weight copies (static, no allocs): 64MB + 16MB + 8MB
__device__ uint4 g_outW[(size_t)V*H/8];
__device__ uint4 g_dWih[(size_t)4*H*2*H/8];
__device__ uint4 g_dWhh[(size_t)4*H*H/8];

// ---------------- init (graph node 1) ----------------
__global__ void init_kernel() {
    int t = threadIdx.x;
    if (t == 0) { g_count = 0; g_epoch = 0; }
    g_h[0][t] = 0.f; g_h[1][t] = 0.f;
    g_xin[t] = 0.f;  g_xin[H + t] = 0.f;
}

// ---------------- fp32 -> fp16 weight conversion (graph node 2) ----------------
__global__ void prep_kernel(const float* __restrict__ outW,
                            const float* __restrict__ dWih,
                            const float* __restrict__ dWhh)
{
    size_t stride = (size_t)gridDim.x * blockDim.x;
    size_t t0 = (size_t)blockIdx.x * blockDim.x + threadIdx.x;
    uint2* oW = (uint2*)g_outW;
    uint2* dI = (uint2*)g_dWih;
    uint2* dH = (uint2*)g_dWhh;
    for (size_t i = t0; i < (size_t)V*H/4; i += stride) {
        float4 f = ((const float4*)outW)[i];
        __half2 a = __floats2half2_rn(f.x, f.y), b = __floats2half2_rn(f.z, f.w);
        oW[i] = make_uint2(*(unsigned*)&a, *(unsigned*)&b);
    }
    for (size_t i = t0; i < (size_t)4*H*2*H/4; i += stride) {
        float4 f = ((const float4*)dWih)[i];
        __half2 a = __floats2half2_rn(f.x, f.y), b = __floats2half2_rn(f.z, f.w);
        dI[i] = make_uint2(*(unsigned*)&a, *(unsigned*)&b);
    }
    for (size_t i = t0; i < (size_t)4*H*H/4; i += stride) {
        float4 f = ((const float4*)dWhh)[i];
        __half2 a = __floats2half2_rn(f.x, f.y), b = __floats2half2_rn(f.z, f.w);
        dH[i] = make_uint2(*(unsigned*)&a, *(unsigned*)&b);
    }
}

// ---------------- helpers ----------------
__device__ __forceinline__ void gsync(unsigned target) {
    __syncthreads();
    if (threadIdx.x == 0) {
        __threadfence();
        if (atomicAdd(&g_count, 1u) == gridDim.x - 1u) {
            g_count = 0;
            __threadfence();
            g_epoch = target;
        } else {
            while (g_epoch < target) { }
        }
    }
    __syncthreads();
}

__device__ __forceinline__ float warp_red(float v) {
    #pragma unroll
    for (int o = 16; o > 0; o >>= 1) v += __shfl_down_sync(0xffffffffu, v, o);
    return v;
}

__device__ __forceinline__ float dot4(const float4 w, const float4 a) {
    return fmaf(w.x, a.x, fmaf(w.y, a.y, fmaf(w.z, a.z, w.w * a.w)));
}

// 8 fp16 weights (uint4) dotted with 8 fp32 activations at s[2k], s[2k+1]
__device__ __forceinline__ float dot8h(uint4 q, const float4* __restrict__ s, int k) {
    float2 f0 = __half22float2(*(__half2*)&q.x);
    float2 f1 = __half22float2(*(__half2*)&q.y);
    float2 f2 = __half22float2(*(__half2*)&q.z);
    float2 f3 = __half22float2(*(__half2*)&q.w);
    float4 v0 = s[2*k], v1 = s[2*k+1];
    float r = fmaf(f0.x, v0.x, fmaf(f0.y, v0.y, fmaf(f1.x, v0.z, f1.y * v0.w)));
    return fmaf(f2.x, v1.x, fmaf(f2.y, v1.y, fmaf(f3.x, v1.z, fmaf(f3.y, v1.w, r))));
}

// w1 @ h -> g_w1h, executed by blocks 0..31 (warp per row)
__device__ __forceinline__ void w1h_phase(int b, int tid, int warp, int lane,
                                          const float* hsrc, float* s_h,
                                          const float* __restrict__ w1) {
    float4* sh = (float4*)s_h;
    const float4* hv = (const float4*)hsrc;
    for (int k = tid; k < H4; k += NT) sh[k] = __ldcg(hv + k);
    __syncthreads();
    int r = b * 32 + warp;
    const float4* wr = (const float4*)(w1 + (size_t)r * H);
    float s = 0.f;
    #pragma unroll 4
    for (int k = lane; k < H4; k += 32) s += dot4(wr[k], sh[k]);
    s = warp_red(s);
    if (lane == 0) g_w1h[r] = s;
}

// ---------------- the whole model (graph node 3) ----------------
__global__ void __launch_bounds__(NT, 1) model_kernel(
    const int*   __restrict__ seq,   const float* __restrict__ embeds,
    const float* __restrict__ eWih,  const float* __restrict__ eWhh,
    const float* __restrict__ ebih,  const float* __restrict__ ebhh,
    const float* __restrict__ dbih,  const float* __restrict__ dbhh,
    const float* __restrict__ outb,
    const float* __restrict__ v,     const float* __restrict__ w1,
    const float* __restrict__ w2,
    float* __restrict__ out, float* __restrict__ out_seq)
{
    const int b = blockIdx.x, tid = threadIdx.x;
    const int warp = tid >> 5, lane = tid & 31;
    const int gg_ = warp >> 3, uu_ = warp & 7;        // gate / unit ownership
    unsigned ep = 0;

    __shared__ float s_vec[2*H];                 // 8 KB staged xin / x
    __shared__ float s_h[H];                     // 4 KB staged h / w1h / E-row
    __shared__ float s_sc[L];                    // 1 KB scores
    __shared__ float s_red[32];
    __shared__ float s_red2[32];
    __shared__ unsigned long long s_key[32];
    __shared__ float s_r2[NT];                   // 4 KB group reductions
    __shared__ float s_c[8];                     // block-local cell state

    if (tid < 8) s_c[tid] = 0.f;

    // ---- embedding gather ----
    for (int t = b; t < L; t += NB) {
        int id = seq[t];
        const float* src = embeds + (size_t)id * H;
        for (int k = tid; k < H; k += NT) g_xemb[t*H + k] = src[k];
    }
    gsync(++ep);

    // ---- encoder: 256 steps, 1 barrier each (block owns its 8 units' gates) ----
    for (int t = 0; t < L; t++) {
        const float4* xv = (const float4*)(g_xemb + t*H);
        const float4* hv = (const float4*)g_h[t & 1];
        float4* sx = (float4*)s_vec;
        float4* sh = (float4*)s_h;
        for (int k = tid; k < H4; k += NT) { sx[k] = xv[k]; sh[k] = __ldcg(hv + k); }
        __syncthreads();
        int j = b * 8 + uu_;
        int r = gg_ * H + j;
        const float4* wi = (const float4*)(eWih + (size_t)r * H);
        const float4* wh = (const float4*)(eWhh + (size_t)r * H);
        float s = 0.f;
        #pragma unroll 4
        for (int k = lane; k < H4; k += 32) {
            s += dot4(wi[k], sx[k]);
            s += dot4(wh[k], sh[k]);
        }
        s = warp_red(s);
        if (lane == 0) s_red2[warp] = s;
        __syncthreads();
        if (tid < 8) {
            int jj = b * 8 + tid;
            float gi = s_red2[tid]      + ebih[jj]       + ebhh[jj];
            float gf = s_red2[8 + tid]  + ebih[H + jj]   + ebhh[H + jj];
            float gG = s_red2[16 + tid] + ebih[2*H + jj] + ebhh[2*H + jj];
            float go = s_red2[24 + tid] + ebih[3*H + jj] + ebhh[3*H + jj];
            float i_ = 1.f / (1.f + expf(-gi));
            float f_ = 1.f / (1.f + expf(-gf));
            float o_ = 1.f / (1.f + expf(-go));
            float cn = f_ * s_c[tid] + i_ * tanhf(gG);
            float hn = o_ * tanhf(cn);
            s_c[tid] = cn;
            g_h[(t+1)&1][jj] = hn;
            g_E[t*H + jj] = hn;
        }
        gsync(++ep);
    }

    // ---- Ew2 = E @ w2^T (one-time): block b does E rows 2b, 2b+1 ----
    for (int rr = 0; rr < 2; rr++) {
        int i = 2*b + rr;
        const float4* Er = (const float4*)(g_E + i*H);
        float4* sh = (float4*)s_h;
        for (int k = tid; k < H4; k += NT) sh[k] = Er[k];
        __syncthreads();
        for (int j = warp; j < H; j += 32) {
            const float4* wr = (const float4*)(w2 + (size_t)j * H);
            float s = 0.f;
            #pragma unroll 4
            for (int k = lane; k < H4; k += 32) s += dot4(wr[k], sh[k]);
            s = warp_red(s);
            if (lane == 0) g_Ew2[i*H + j] = s;
        }
        __syncthreads();
    }
    gsync(++ep);

    // ---- A0: w1 @ h for first decoder step ----
    if (b < 32) w1h_phase(b, tid, warp, lane, g_h[0], s_h, w1);
    gsync(++ep);

    // ---- decoder: 256 steps, 5 barriers each ----
    for (int d = 0; d < L; d++) {
        const int pin = d & 1, pout = (d + 1) & 1;

        // B: scores_i = v . tanh(w1h + Ew2[i])   (block b -> rows 2b, 2b+1)
        {
            float4* sh = (float4*)s_h;
            const float4* wv = (const float4*)g_w1h;
            for (int k = tid; k < H4; k += NT) sh[k] = __ldcg(wv + k);
            __syncthreads();
            for (int rr = 0; rr < 2; rr++) {
                int i = 2*b + rr;
                float val = v[tid] * tanhf(s_h[tid] + g_Ew2[i*H + tid]);
                val = warp_red(val);
                if (lane == 0) s_red[warp] = val;
                __syncthreads();
                if (warp == 0) {
                    float x = warp_red(s_red[lane]);
                    if (lane == 0) g_scores[i] = x;
                }
                __syncthreads();
            }
        }
        gsync(++ep);

        // C: softmax (redundant per block) + ctx slice -> g_xin[H..)
        {
            if (tid < L) s_sc[tid] = __ldcg(g_scores + tid);
            __syncthreads();
            float mval = (tid < L) ? s_sc[tid] : -3.0e38f;
            #pragma unroll
            for (int o = 16; o > 0; o >>= 1)
                mval = fmaxf(mval, __shfl_down_sync(0xffffffffu, mval, o));
            if (lane == 0) s_red[warp] = mval;
            __syncthreads();
            if (tid == 0) {
                float mm = s_red[0];
                for (int w_ = 1; w_ < 32; w_++) mm = fmaxf(mm, s_red[w_]);
                s_red[0] = mm;
            }
            __syncthreads();
            float mx = s_red[0];
            float ev = 0.f;
            if (tid < L) { ev = expf(s_sc[tid] - mx); }
            __syncthreads();
            if (tid < L) s_sc[tid] = ev;
            float sv2 = warp_red(ev);
            if (lane == 0) s_red[warp] = sv2;
            __syncthreads();
            if (tid == 0) {
                float ss = 0.f;
                for (int w_ = 0; w_ < 32; w_++) ss += s_red[w_];
                s_red[0] = 1.f / ss;
            }
            __syncthreads();
            float inv = s_red[0];
            int q = tid >> 7, ii = tid & 127;
            int j = b * 8 + q;
            float acc = s_sc[ii]       * g_E[ii*H + j]
                      + s_sc[ii + 128] * g_E[(ii + 128)*H + j];
            s_r2[tid] = acc;
            __syncthreads();
            for (int st = 64; st > 0; st >>= 1) {
                if (ii < st) s_r2[tid] += s_r2[tid + st];
                __syncthreads();
            }
            if (ii == 0) g_xin[H + j] = s_r2[tid] * inv;
        }
        gsync(++ep);

        // D: decoder LSTM gates (fp16 weights, block-local combine) — 1 barrier
        {
            float4* sv = (float4*)s_vec;
            float4* sh = (float4*)s_h;
            const float4* xv = (const float4*)g_xin;
            const float4* hv = (const float4*)g_h[pin];
            for (int k = tid; k < 2*H4; k += NT) sv[k] = __ldcg(xv + k);
            for (int k = tid; k < H4;   k += NT) sh[k] = __ldcg(hv + k);
            __syncthreads();
            int j = b * 8 + uu_;
            int r = gg_ * H + j;
            const uint4* wi = g_dWih + (size_t)r * (2*H/8);
            const uint4* wh = g_dWhh + (size_t)r * (H/8);
            float s = 0.f;
            #pragma unroll 4
            for (int k = lane; k < 2*H/8; k += 32) s += dot8h(wi[k], sv, k);
            #pragma unroll 4
            for (int k = lane; k < H/8;   k += 32) s += dot8h(wh[k], sh, k);
            s = warp_red(s);
            if (lane == 0) s_red2[warp] = s;
            __syncthreads();
            if (tid < 8) {
                int jj = b * 8 + tid;
                float gi = s_red2[tid]      + dbih[jj]       + dbhh[jj];
                float gf = s_red2[8 + tid]  + dbih[H + jj]   + dbhh[H + jj];
                float gG = s_red2[16 + tid] + dbih[2*H + jj] + dbhh[2*H + jj];
                float go = s_red2[24 + tid] + dbih[3*H + jj] + dbhh[3*H + jj];
                float i_ = 1.f / (1.f + expf(-gi));
                float f_ = 1.f / (1.f + expf(-gf));
                float o_ = 1.f / (1.f + expf(-go));
                float cn = f_ * s_c[tid] + i_ * tanhf(gG);
                float hn = o_ * tanhf(cn);
                s_c[tid] = cn;
                g_h[pout][jj] = hn;
            }
        }
        gsync(++ep);

        // E: logits = out_W(fp16,L2-resident) @ h_new + out_b + block argmax partial
        {
            float4* sh = (float4*)s_h;
            const float4* hv = (const float4*)g_h[pout];
            for (int k = tid; k < H4; k += NT) sh[k] = __ldcg(hv + k);
            __syncthreads();
            float bestv = -3.0e38f; int bestr = 0;
            float* od = out + (size_t)d * V;
            for (int r = b * 32 + warp; r < V; r += NB * 32) {
                const uint4* wr = g_outW + (size_t)r * (H/8);
                float s = 0.f;
                #pragma unroll
                for (int k = lane; k < H/8; k += 32) s += dot8h(wr[k], sh, k);
                s = warp_red(s);
                if (lane == 0) {
                    s += outb[r];
                    od[r] = s;
                    if (s > bestv) { bestv = s; bestr = r; }   // rows ascend -> first max kept
                }
            }
            if (lane == 0) {
                unsigned u = __float_as_uint(bestv);
                u = (u & 0x80000000u) ? ~u : (u | 0x80000000u);
                s_key[warp] = ((unsigned long long)u << 32) |
                              (unsigned long long)(0xFFFFFFFFu - (unsigned)bestr);
            }
            __syncthreads();
            if (tid == 0) {
                unsigned long long kk = s_key[0];
                for (int w_ = 1; w_ < 32; w_++) if (s_key[w_] > kk) kk = s_key[w_];
                g_part[b] = kk;
            }
        }
        gsync(++ep);

        // F || A': blocks 0..31 next-step w1h; blocks 32..40 argmax finalize + feedback
        if (b < 32) {
            w1h_phase(b, tid, warp, lane, g_h[pout], s_h, w1);
        } else if (b < 41) {
            unsigned long long kk = (tid < NB) ? __ldcg(g_part + tid) : 0ull;
            #pragma unroll
            for (int o = 16; o > 0; o >>= 1) {
                unsigned long long ok = __shfl_down_sync(0xffffffffu, kk, o);
                if (ok > kk) kk = ok;
            }
            if (lane == 0) s_key[warp] = kk;
            __syncthreads();
            if (tid == 0) {
                unsigned long long m2 = s_key[0];
                for (int w_ = 1; w_ < 32; w_++) if (s_key[w_] > m2) m2 = s_key[w_];
                s_key[0] = m2;
            }
            __syncthreads();
            int idx = (int)(0xFFFFFFFFu - (unsigned)(s_key[0] & 0xFFFFFFFFull));
            if (b == 40) {
                if (tid == 0 && out_seq) out_seq[d] = (float)idx;
            } else {
                int base = (b - 32) * 128;
                if (tid < 128) {
                    float e = embeds[(size_t)idx * H + base + tid];
                    g_xin[base + tid] = fmaxf(e, 0.f);
                }
            }
        }
        gsync(++ep);
    }
}

// ---------------- launch: 3-node graph ----------------
extern "C" void kernel_launch(void* const* d_in, const int* in_sizes, int n_in,
                              void* d_out, int out_size)
{
    const int*   seq    = (const int*)  d_in[0];
    const float* embeds = (const float*)d_in[1];
    const float* eWih = (const float*)d_in[2],  *eWhh = (const float*)d_in[3];
    const float* ebih = (const float*)d_in[4],  *ebhh = (const float*)d_in[5];
    const float* dWih = (const float*)d_in[6],  *dWhh = (const float*)d_in[7];
    const float* dbih = (const float*)d_in[8],  *dbhh = (const float*)d_in[9];
    const float* outW = (const float*)d_in[10], *outb = (const float*)d_in[11];
    const float* v    = (const float*)d_in[12];
    const float* w1   = (const float*)d_in[13], *w2   = (const float*)d_in[14];

    float* out = (float*)d_out;
    float* out_seq = (out_size >= L*V + L) ? out + (size_t)L*V : nullptr;

    init_kernel<<<1, NT>>>();
    prep_kernel<<<2048, 256>>>(outW, dWih, dWhh);
    model_kernel<<<NB, NT>>>(seq, embeds, eWih, eWhh, ebih, ebhh,
                             dbih, dbhh, outb, v, w1, w2, out, out_seq);
}